// round 10
// baseline (speedup 1.0000x reference)
#include <cuda_runtime.h>
#include <math.h>

// ---------------------------------------------------------------------------
// Problem constants
// ---------------------------------------------------------------------------
#define B_   2
#define P_   4000
#define NP_  4096
#define D_   64
#define M_   512
#define HW_  214272
#define BITW (HW_ / 32)           // 6696

#define S0_   ((size_t)B_ * 128 * HW_)
#define S2_   ((size_t)B_ * 64 * HW_)
#define OFF1_ (S0_)
#define OFF2_ (2 * S0_)
#define OFF3_ (2 * S0_ + S2_)
#define OFF4_ (OFF3_ + (size_t)B_ * P_ * D_)

// Schedule
#define NTHR   256
#define PPB    128                     // pillars per block (2 threads/pillar)
#define BPB    32                      // blocks per batch (ceil 4000/128)
#define NCH    4                       // point chunks
#define CPTS   (NP_ / NCH)             // 1024
#define TILE_T 64
#define ROWF   68                      // smem row pitch (floats); halves at +0 / +36
#define HOFF   36

#define N_PTB  (B_ * BPB * NCH)        // 256
#define N_MEMB (B_ * BPB)              // 64
#define N_ATT  (N_PTB + N_MEMB)        // 320
#define N_FILL 128
#define NB_TOT 448                     // 64 groups of 7: 2 fill + 5 attn
#define PLANE4 (HW_ / 4)               // 53568
#define N4_    ((size_t)640 * PLANE4)  // 34,283,520 float4
#define FCH    (N4_ / N_FILL)          // 267840 exactly

#define SMEM_BYTES 55296               // attn: 2x17408 tile; fill: 53568 bitmap

__device__ int      g_winner[B_ * HW_];
__device__ unsigned g_bitmap[B_ * BITW];
__device__ float    g_pkv[B_ * P_ * 32];   // point: 4 chunks x 8 candidates
__device__ int      g_pki[B_ * P_ * 32];
__device__ float    g_mkv[B_ * P_ * 8];    // memory: 8 candidates
__device__ int      g_mki[B_ * P_ * 8];

// ---------------------------------------------------------------------------
__device__ __forceinline__ void cp16(void* dst, const void* src) {
    unsigned a = (unsigned)__cvta_generic_to_shared(dst);
    asm volatile("cp.async.cg.shared.global [%0], [%1], 16;" :: "r"(a), "l"(src));
}
__device__ __forceinline__ void cp_commit() {
    asm volatile("cp.async.commit_group;" ::: "memory");
}
__device__ __forceinline__ void cp_wait_all() {
    asm volatile("cp.async.wait_group 0;" ::: "memory");
}
__device__ __forceinline__ void fma2(unsigned long long& acc,
                                     unsigned long long a, unsigned long long b) {
    asm volatile("fma.rn.f32x2 %0, %1, %2, %0;" : "+l"(acc) : "l"(a), "l"(b));
}
__device__ __forceinline__ float pair_sum(unsigned long long v) {
    return __uint_as_float((unsigned)v) + __uint_as_float((unsigned)(v >> 32));
}

// ---------------------------------------------------------------------------
// Tile smem layout: row r at r*ROWF floats; dims [0,32) at +0, [32,64) at +HOFF
// (16B gap keeps the two 16-lane broadcast groups on disjoint banks).
// ---------------------------------------------------------------------------
__device__ __forceinline__ void tile_cp(float* dstbase, const float* src) {
    const int t = threadIdx.x;
#pragma unroll
    for (int q = 0; q < 4; ++q) {
        int lin = t + q * NTHR;
        int r = lin >> 4, c = lin & 15;
        int doff = r * ROWF + ((c < 8) ? c * 4 : HOFF + (c - 8) * 4);
        cp16(dstbase + doff, src + r * D_ + c * 4);
    }
}

// ---------------------------------------------------------------------------
// Per-thread-pair attention: thread owns half (32 dims) of one pillar in regs,
// scans npts candidates from shared tiles, keeps private top-8 in registers.
// Writes top-8 (val, global idx) for h==0 valid pillars.
// ---------------------------------------------------------------------------
__device__ __forceinline__ void attn_run(
    const float* __restrict__ pillars, int b, int p0, int pvalid,
    const float* __restrict__ vb, int npts, int idx_base,
    float* __restrict__ okv, int* __restrict__ oki, int stride, int slot,
    char* smem)
{
    float* s_pt = (float*)smem;
    const int t = threadIdx.x;
    const int h = t & 1;
    const int pl = t >> 1;
    const bool valid = pl < pvalid;
    const unsigned FULL = 0xffffffffu;

    // prefetch tile 0
    tile_cp(s_pt, vb);
    cp_commit();

    // pillar half -> 16 packed pairs (32 regs)
    const float* pg = pillars + ((size_t)b * P_ + p0 + (valid ? pl : 0)) * D_ + h * 32;
    unsigned long long pil2[16];
#pragma unroll
    for (int k = 0; k < 8; ++k) {
        ulonglong2 q = *(const ulonglong2*)(pg + 4 * k);
        pil2[2 * k] = q.x; pil2[2 * k + 1] = q.y;
    }

    float tv[8]; int ti[8];
#pragma unroll
    for (int k = 0; k < 8; ++k) { tv[k] = -INFINITY; ti[k] = 0; }
    float vmin = -INFINITY;
    int   am = 0;

    const int NT = npts / TILE_T;
#pragma unroll 1
    for (int tile = 0; tile < NT; ++tile) {
        float* buf = s_pt + (tile & 1) * (TILE_T * ROWF);
        cp_wait_all();
        __syncthreads();
        if (tile + 1 < NT) {
            tile_cp(s_pt + ((tile + 1) & 1) * (TILE_T * ROWF),
                    vb + (size_t)(tile + 1) * TILE_T * D_);
            cp_commit();
        }

#pragma unroll 1
        for (int g = 0; g < 8; ++g) {          // 8 groups of 8 points
            unsigned long long acc[8];
#pragma unroll
            for (int j = 0; j < 8; ++j) acc[j] = 0ull;
            const float* base = buf + (g * 8) * ROWF + h * HOFF;

#pragma unroll
            for (int dc = 0; dc < 8; ++dc) {   // 4 dims per step
                ulonglong2 x[4];
#pragma unroll
                for (int jj = 0; jj < 4; ++jj)
                    x[jj] = *(const ulonglong2*)(base + jj * ROWF + dc * 4);
#pragma unroll
                for (int jj = 0; jj < 4; ++jj) fma2(acc[jj], pil2[2 * dc], x[jj].x);
#pragma unroll
                for (int jj = 0; jj < 4; ++jj) fma2(acc[jj], pil2[2 * dc + 1], x[jj].y);
#pragma unroll
                for (int jj = 0; jj < 4; ++jj)
                    x[jj] = *(const ulonglong2*)(base + (4 + jj) * ROWF + dc * 4);
#pragma unroll
                for (int jj = 0; jj < 4; ++jj) fma2(acc[4 + jj], pil2[2 * dc], x[jj].x);
#pragma unroll
                for (int jj = 0; jj < 4; ++jj) fma2(acc[4 + jj], pil2[2 * dc + 1], x[jj].y);
            }

            // combine halves + private top-8
#pragma unroll
            for (int j = 0; j < 8; ++j) {
                float s = pair_sum(acc[j]);
                s += __shfl_xor_sync(FULL, s, 1);
                if (s > vmin) {
                    tv[am] = s;
                    ti[am] = idx_base + tile * TILE_T + g * 8 + j;
                    float mn = tv[0]; int a2 = 0;
#pragma unroll
                    for (int k = 1; k < 8; ++k)
                        if (tv[k] < mn) { mn = tv[k]; a2 = k; }
                    vmin = mn; am = a2;
                }
            }
        }
    }

    if (h == 0 && valid) {
        size_t o = (size_t)(b * P_ + p0 + pl) * stride + slot;
#pragma unroll
        for (int k = 0; k < 8; ++k) { okv[o + k] = tv[k]; oki[o + k] = ti[k]; }
    }
}

// ---------------------------------------------------------------------------
// Fill role: contiguous float4 range with winner materialization of the
// static planes. Bitmap loaded into smem ONCE per block.
// ---------------------------------------------------------------------------
__device__ void fill_range(int fid, const float* __restrict__ pillars,
                           const float* __restrict__ scale,
                           float* __restrict__ out, char* smem)
{
    unsigned* s_bm = (unsigned*)smem;
    const int t = threadIdx.x;
    for (int i = t; i < B_ * BITW; i += NTHR) s_bm[i] = g_bitmap[i];
    __syncthreads();

    size_t beg = (size_t)fid * FCH;
    size_t end = beg + FCH; if (end > N4_) end = N4_;
    float4* o4 = (float4*)out;

    for (size_t f = beg + t; f < end; f += NTHR) {
        int plane = (int)(f / PLANE4);          // 0..639
        int col4  = ((int)(f - (size_t)plane * PLANE4)) << 2;
        float4 v = make_float4(0.f, 0.f, 0.f, 0.f);
        int b, ch;
        const float* src;
        bool stat;
        if (plane < 512) {
            int pl = plane & 255;
            b = pl >> 7; ch = pl & 127;
            stat = ch < 64; src = pillars;
        } else {
            int pl = plane - 512;
            b = pl >> 6; ch = pl & 63;
            stat = true; src = scale;
        }
        if (stat) {
            unsigned bits = (s_bm[b * BITW + (col4 >> 5)] >> (col4 & 31)) & 0xFu;
            if (bits) {
                int colb = b * HW_ + col4;
                if (bits & 1u) { int w = g_winner[colb];     v.x = src[((size_t)(b * P_ + w)) * D_ + ch]; }
                if (bits & 2u) { int w = g_winner[colb + 1]; v.y = src[((size_t)(b * P_ + w)) * D_ + ch]; }
                if (bits & 4u) { int w = g_winner[colb + 2]; v.z = src[((size_t)(b * P_ + w)) * D_ + ch]; }
                if (bits & 8u) { int w = g_winner[colb + 3]; v.w = src[((size_t)(b * P_ + w)) * D_ + ch]; }
            }
        }
        __stcs(o4 + f, v);
    }
}

// ---------------------------------------------------------------------------
// Fused kernel: 64 groups of 7 blocks = 2 fill + 5 attention.
// attn id: [0,256) point chunk blocks, [256,320) memory blocks.
// ---------------------------------------------------------------------------
__global__ void __launch_bounds__(NTHR, 2)
fused_kernel(const float* __restrict__ pillars,
             const float* __restrict__ scale,
             const float* __restrict__ points,
             const float* __restrict__ W,
             float* __restrict__ out)
{
    extern __shared__ char smem[];
    const int grp = blockIdx.x / 7;
    const int ln  = blockIdx.x % 7;
    if (ln < 2) {
        fill_range(grp * 2 + ln, pillars, scale, out, smem);
        return;
    }
    const int aid = grp * 5 + (ln - 2);
    if (aid < N_PTB) {
        const int chunk = aid >> 6;            // 0..3
        const int r     = aid & 63;
        const int b     = r >> 5;
        const int blk   = r & 31;
        const int p0    = blk * PPB;
        const int pvalid = min(PPB, P_ - p0);
        attn_run(pillars, b, p0, pvalid,
                 points + ((size_t)b * NP_ + (size_t)chunk * CPTS) * D_,
                 CPTS, chunk * CPTS,
                 g_pkv, g_pki, 32, chunk * 8, smem);
    } else {
        const int mid = aid - N_PTB;
        const int b   = mid >> 5;
        const int blk = mid & 31;
        const int p0  = blk * PPB;
        const int pvalid = min(PPB, P_ - p0);
        attn_run(pillars, b, p0, pvalid, W, M_, 0,
                 g_mkv, g_mki, 8, 0, smem);
    }
}

// ---------------------------------------------------------------------------
// Merge: one warp per (pillar, branch). w < 8000: point pillar (32 cands,
// gather from points, write out3). w >= 8000: memory pillar (8 cands, gather
// from W, write out4).
// ---------------------------------------------------------------------------
__global__ void __launch_bounds__(256)
merge_kernel(const float* __restrict__ points, const float* __restrict__ W,
             float* __restrict__ out)
{
    const int w  = blockIdx.x * 8 + (threadIdx.x >> 5);
    const int tx = threadIdx.x & 31;
    if (w >= 2 * B_ * P_) return;
    const unsigned FULL = 0xffffffffu;
    const bool isMem = w >= B_ * P_;
    const int bp = isMem ? w - B_ * P_ : w;
    const int b  = bp / P_;
    const float* vb = isMem ? W : points + (size_t)b * NP_ * D_;

    float v; int ii;
    if (isMem) {
        v  = (tx < 8) ? g_mkv[(size_t)bp * 8 + tx] : -INFINITY;
        ii = (tx < 8) ? g_mki[(size_t)bp * 8 + tx] : 0;
    } else {
        v  = g_pkv[(size_t)bp * 32 + tx];
        ii = g_pki[(size_t)bp * 32 + tx];
    }

    float vals[8]; int ids[8];
#pragma unroll
    for (int k = 0; k < 8; ++k) {
        float m = v;
#pragma unroll
        for (int off = 16; off; off >>= 1)
            m = fmaxf(m, __shfl_xor_sync(FULL, m, off));
        unsigned ball = __ballot_sync(FULL, v == m);
        int sel = __ffs(ball) - 1;
        ids[k] = __shfl_sync(FULL, ii, sel);
        vals[k] = m;
        if (tx == sel) v = -INFINITY;
    }

    float mx = vals[0];
#pragma unroll
    for (int k = 1; k < 8; ++k) mx = fmaxf(mx, vals[k]);
    float wt[8], ssum = 0.f;
#pragma unroll
    for (int k = 0; k < 8; ++k) { wt[k] = expf(vals[k] - mx); ssum += wt[k]; }
    float inv = 1.f / ssum;
    float a0 = 0.f, a1 = 0.f;
#pragma unroll
    for (int k = 0; k < 8; ++k) {
        const float* vp = vb + (size_t)ids[k] * D_;
        float wk = wt[k] * inv;
        a0 += wk * vp[tx];
        a1 += wk * vp[tx + 32];
    }
    float* op = out + (isMem ? OFF4_ : OFF3_) + (size_t)bp * D_;
    op[tx] = a0;
    op[tx + 32] = a1;
}

// ---------------------------------------------------------------------------
__global__ void pre1_kernel() {
    int i = blockIdx.x * blockDim.x + threadIdx.x;
    if (i < B_ * HW_) g_winner[i] = -1;
    if (i < B_ * BITW) g_bitmap[i] = 0u;
}
__global__ void pre2_kernel(const int* __restrict__ idx) {
    int i = blockIdx.x * blockDim.x + threadIdx.x;
    if (i < B_ * P_) {
        int b = i / P_;
        int col = idx[i];
        atomicMax(&g_winner[b * HW_ + col], i - b * P_);
        atomicOr(&g_bitmap[b * BITW + (col >> 5)], 1u << (col & 31));
    }
}

// pos planes: winner pillars write pos_mem -> out0 upper, pos_point -> out1 upper
__global__ void __launch_bounds__(256)
pos_scatter_kernel(const int* __restrict__ idx, float* __restrict__ out)
{
    const int warp0 = blockIdx.x * 8 + (threadIdx.x >> 5);
    const int tx = threadIdx.x & 31;
    for (int bp = warp0; bp < B_ * P_; bp += gridDim.x * 8) {
        int b = (bp >= P_) ? 1 : 0;
        int p = bp - b * P_;
        int col = idx[bp];
        if (g_winner[b * HW_ + col] != p) continue;
        float mv0 = out[OFF4_ + (size_t)bp * D_ + tx];
        float mv1 = out[OFF4_ + (size_t)bp * D_ + tx + 32];
        float qv0 = out[OFF3_ + (size_t)bp * D_ + tx];
        float qv1 = out[OFF3_ + (size_t)bp * D_ + tx + 32];
        size_t g0 = (size_t)b * 128 * HW_ + (size_t)(64 + tx) * HW_ + col;
        out[g0] = mv0;
        out[g0 + (size_t)32 * HW_] = mv1;
        out[OFF1_ + g0] = qv0;
        out[OFF1_ + g0 + (size_t)32 * HW_] = qv1;
    }
}

// ---------------------------------------------------------------------------
extern "C" void kernel_launch(void* const* d_in, const int* in_sizes, int n_in,
                              void* d_out, int out_size) {
    (void)in_sizes; (void)n_in; (void)out_size;
    const float* pillars = (const float*)d_in[0];
    const float* scale   = (const float*)d_in[1];
    const float* points  = (const float*)d_in[2];
    const float* W       = (const float*)d_in[3];
    const int*   idx     = (const int*)d_in[4];
    float* out = (float*)d_out;

    cudaFuncSetAttribute(fused_kernel,
                         cudaFuncAttributeMaxDynamicSharedMemorySize, SMEM_BYTES);

    pre1_kernel<<<(B_ * HW_ + 255) / 256, 256>>>();
    pre2_kernel<<<(B_ * P_ + 255) / 256, 256>>>(idx);
    fused_kernel<<<NB_TOT, NTHR, SMEM_BYTES>>>(pillars, scale, points, W, out);
    merge_kernel<<<(2 * B_ * P_ + 7) / 8, 256>>>(points, W, out);
    pos_scatter_kernel<<<125, 256>>>(idx, out);
}

// round 11
// speedup vs baseline: 1.1351x; 1.1351x over previous
#include <cuda_runtime.h>
#include <math.h>

// ---------------------------------------------------------------------------
// Problem constants
// ---------------------------------------------------------------------------
#define B_   2
#define P_   4000
#define NP_  4096
#define D_   64
#define M_   512
#define HW_  214272
#define BITW (HW_ / 32)           // 6696

#define S0_   ((size_t)B_ * 128 * HW_)
#define S2_   ((size_t)B_ * 64 * HW_)
#define OFF1_ (S0_)
#define OFF2_ (2 * S0_)
#define OFF3_ (2 * S0_ + S2_)
#define OFF4_ (OFF3_ + (size_t)B_ * P_ * D_)

// Schedule
#define NTHR   256
#define PPB    128                     // pillars per block (2 threads/pillar)
#define BPB    32                      // blocks per batch
#define NCH    4                       // point chunks
#define CPTS   (NP_ / NCH)             // 1024
#define TILE_T 64                      // points per smem tile (flat 16KB)

#define N_PTB  (B_ * BPB * NCH)        // 256
#define N_MEMB (B_ * BPB)              // 64
#define N_FILL 128
#define NB_TOT 448                     // 64 groups of 7: 2 fill + 5 attn
#define PLANE4 (HW_ / 4)               // 53568
#define N4_    ((size_t)640 * PLANE4)  // 34,283,520 float4
#define FCH    (N4_ / N_FILL)          // 267840 exactly

#define SMEM_BYTES 55296               // attn: 2x16KB tiles; fill: 53568B bitmap

__device__ int      g_winner[B_ * HW_];
__device__ unsigned g_bitmap[B_ * BITW];
__device__ float    g_pkv[B_ * P_ * 32];   // point: 4 chunks x 8 candidates
__device__ int      g_pki[B_ * P_ * 32];
__device__ float    g_mkv[B_ * P_ * 8];    // memory: 8 candidates
__device__ int      g_mki[B_ * P_ * 8];

// ---------------------------------------------------------------------------
__device__ __forceinline__ void cp16(void* dst, const void* src) {
    unsigned a = (unsigned)__cvta_generic_to_shared(dst);
    asm volatile("cp.async.cg.shared.global [%0], [%1], 16;" :: "r"(a), "l"(src));
}
__device__ __forceinline__ void cp_commit() {
    asm volatile("cp.async.commit_group;" ::: "memory");
}
__device__ __forceinline__ void cp_wait_all() {
    asm volatile("cp.async.wait_group 0;" ::: "memory");
}
__device__ __forceinline__ void fma2(unsigned long long& acc,
                                     unsigned long long a, unsigned long long b) {
    asm volatile("fma.rn.f32x2 %0, %1, %2, %0;" : "+l"(acc) : "l"(a), "l"(b));
}
__device__ __forceinline__ float pair_sum(unsigned long long v) {
    return __uint_as_float((unsigned)v) + __uint_as_float((unsigned)(v >> 32));
}

// flat 16KB tile copy (64 rows x 256B contiguous)
__device__ __forceinline__ void tile_cp(float* dst, const float* src) {
    const int t = threadIdx.x;
#pragma unroll
    for (int q = 0; q < 4; ++q) {
        int lin = (t + q * NTHR) * 4;
        cp16(dst + lin, src + lin);
    }
}

// ---------------------------------------------------------------------------
// Per-thread-pair attention. Thread owns half (32 dims) of one pillar in regs;
// scans npts candidates from broadcast smem tiles; keeps a STATICALLY-indexed
// sorted top-8 in registers (guard: one compare; insert: unrolled compare-swap
// chain -- no dynamic register indexing, no local memory).
// ---------------------------------------------------------------------------
__device__ void attn_run(
    const float* __restrict__ pillars, int b, int p0, int pvalid,
    const float* __restrict__ vb, int npts, int idx_base,
    float* __restrict__ okv, int* __restrict__ oki, int stride, int slot,
    char* smem)
{
    float* s_pt = (float*)smem;
    const int t  = threadIdx.x;
    const int h  = t & 1;
    const int pl = t >> 1;
    const bool valid = pl < pvalid;
    const unsigned FULL = 0xffffffffu;

    // prefetch tile 0
    tile_cp(s_pt, vb);
    cp_commit();

    // pillar half -> 16 packed pairs (32 regs)
    const float* pg = pillars + ((size_t)b * P_ + p0 + (valid ? pl : 0)) * D_ + h * 32;
    unsigned long long pil[16];
#pragma unroll
    for (int k = 0; k < 8; ++k) {
        ulonglong2 q = *(const ulonglong2*)(pg + 4 * k);
        pil[2 * k] = q.x; pil[2 * k + 1] = q.y;
    }

    float tv[8]; int ti[8];
#pragma unroll
    for (int k = 0; k < 8; ++k) { tv[k] = -INFINITY; ti[k] = 0; }

    const int NT = npts / TILE_T;
#pragma unroll 1
    for (int tile = 0; tile < NT; ++tile) {
        float* buf = s_pt + (tile & 1) * (TILE_T * D_);
        cp_wait_all();
        __syncthreads();
        if (tile + 1 < NT) {
            tile_cp(s_pt + ((tile + 1) & 1) * (TILE_T * D_),
                    vb + (size_t)(tile + 1) * TILE_T * D_);
            cp_commit();
        }

#pragma unroll 1
        for (int g = 0; g < TILE_T / 2; ++g) {       // 2 points per step
            const float* r0 = buf + (2 * g) * D_ + h * 32;
            const float* r1 = r0 + D_;
            unsigned long long a0 = 0ull, a1 = 0ull;
#pragma unroll
            for (int d = 0; d < 8; ++d) {
                ulonglong2 x0 = *(const ulonglong2*)(r0 + 4 * d);
                ulonglong2 x1 = *(const ulonglong2*)(r1 + 4 * d);
                fma2(a0, pil[2 * d],     x0.x);
                fma2(a1, pil[2 * d],     x1.x);
                fma2(a0, pil[2 * d + 1], x0.y);
                fma2(a1, pil[2 * d + 1], x1.y);
            }
            float s0 = pair_sum(a0);
            float s1 = pair_sum(a1);
            s0 += __shfl_xor_sync(FULL, s0, 1);
            s1 += __shfl_xor_sync(FULL, s1, 1);
            const int id0 = idx_base + tile * TILE_T + 2 * g;

            // static sorted-list insert (descending); hot path = 1 compare
            if (s0 > tv[7]) {
                tv[7] = s0; ti[7] = id0;
#pragma unroll
                for (int k = 7; k >= 1; --k)
                    if (tv[k] > tv[k - 1]) {
                        float f = tv[k - 1]; tv[k - 1] = tv[k]; tv[k] = f;
                        int q = ti[k - 1]; ti[k - 1] = ti[k]; ti[k] = q;
                    }
            }
            if (s1 > tv[7]) {
                tv[7] = s1; ti[7] = id0 + 1;
#pragma unroll
                for (int k = 7; k >= 1; --k)
                    if (tv[k] > tv[k - 1]) {
                        float f = tv[k - 1]; tv[k - 1] = tv[k]; tv[k] = f;
                        int q = ti[k - 1]; ti[k - 1] = ti[k]; ti[k] = q;
                    }
            }
        }
    }

    if (h == 0 && valid) {
        size_t o = (size_t)(b * P_ + p0 + pl) * stride + slot;
#pragma unroll
        for (int k = 0; k < 8; ++k) { okv[o + k] = tv[k]; oki[o + k] = ti[k]; }
    }
}

// ---------------------------------------------------------------------------
// Fill role: contiguous float4 range with winner materialization of the
// static planes. Bitmap loaded into smem ONCE per block.
// ---------------------------------------------------------------------------
__device__ void fill_range(int fid, const float* __restrict__ pillars,
                           const float* __restrict__ scale,
                           float* __restrict__ out, char* smem)
{
    unsigned* s_bm = (unsigned*)smem;
    const int t = threadIdx.x;
    for (int i = t; i < B_ * BITW; i += NTHR) s_bm[i] = g_bitmap[i];
    __syncthreads();

    size_t beg = (size_t)fid * FCH;
    size_t end = beg + FCH; if (end > N4_) end = N4_;
    float4* o4 = (float4*)out;

    for (size_t f = beg + t; f < end; f += NTHR) {
        int plane = (int)(f / PLANE4);          // 0..639
        int col4  = ((int)(f - (size_t)plane * PLANE4)) << 2;
        float4 v = make_float4(0.f, 0.f, 0.f, 0.f);
        int b, ch;
        const float* src;
        bool stat;
        if (plane < 512) {
            int pl = plane & 255;
            b = pl >> 7; ch = pl & 127;
            stat = ch < 64; src = pillars;
        } else {
            int pl = plane - 512;
            b = pl >> 6; ch = pl & 63;
            stat = true; src = scale;
        }
        if (stat) {
            unsigned bits = (s_bm[b * BITW + (col4 >> 5)] >> (col4 & 31)) & 0xFu;
            if (bits) {
                int colb = b * HW_ + col4;
                if (bits & 1u) { int w = g_winner[colb];     v.x = src[((size_t)(b * P_ + w)) * D_ + ch]; }
                if (bits & 2u) { int w = g_winner[colb + 1]; v.y = src[((size_t)(b * P_ + w)) * D_ + ch]; }
                if (bits & 4u) { int w = g_winner[colb + 2]; v.z = src[((size_t)(b * P_ + w)) * D_ + ch]; }
                if (bits & 8u) { int w = g_winner[colb + 3]; v.w = src[((size_t)(b * P_ + w)) * D_ + ch]; }
            }
        }
        __stcs(o4 + f, v);
    }
}

// ---------------------------------------------------------------------------
// Fused kernel: 64 groups of 7 blocks = 2 fill + 5 attention.
// attn id: [0,256) point chunk blocks, [256,320) memory blocks.
// ---------------------------------------------------------------------------
__global__ void __launch_bounds__(NTHR, 3)
fused_kernel(const float* __restrict__ pillars,
             const float* __restrict__ scale,
             const float* __restrict__ points,
             const float* __restrict__ W,
             float* __restrict__ out)
{
    extern __shared__ char smem[];
    const int grp = blockIdx.x / 7;
    const int ln  = blockIdx.x % 7;
    if (ln < 2) {
        fill_range(grp * 2 + ln, pillars, scale, out, smem);
        return;
    }
    const int aid = grp * 5 + (ln - 2);
    if (aid < N_PTB) {
        const int chunk = aid >> 6;            // 0..3
        const int r     = aid & 63;
        const int b     = r >> 5;
        const int blk   = r & 31;
        const int p0    = blk * PPB;
        const int pvalid = min(PPB, P_ - p0);
        attn_run(pillars, b, p0, pvalid,
                 points + ((size_t)b * NP_ + (size_t)chunk * CPTS) * D_,
                 CPTS, chunk * CPTS,
                 g_pkv, g_pki, 32, chunk * 8, smem);
    } else {
        const int mid = aid - N_PTB;
        const int b   = mid >> 5;
        const int blk = mid & 31;
        const int p0  = blk * PPB;
        const int pvalid = min(PPB, P_ - p0);
        attn_run(pillars, b, p0, pvalid, W, M_, 0,
                 g_mkv, g_mki, 8, 0, smem);
    }
}

// ---------------------------------------------------------------------------
// Merge: one warp per (pillar, branch). w < 8000: point pillar (32 cands from
// 4 chunks, gather from points, write out3). w >= 8000: memory pillar (8
// cands, gather from W, write out4).
// ---------------------------------------------------------------------------
__global__ void __launch_bounds__(256)
merge_kernel(const float* __restrict__ points, const float* __restrict__ W,
             float* __restrict__ out)
{
    const int w  = blockIdx.x * 8 + (threadIdx.x >> 5);
    const int tx = threadIdx.x & 31;
    if (w >= 2 * B_ * P_) return;
    const unsigned FULL = 0xffffffffu;
    const bool isMem = w >= B_ * P_;
    const int bp = isMem ? w - B_ * P_ : w;
    const int b  = bp / P_;
    const float* vb = isMem ? W : points + (size_t)b * NP_ * D_;

    float v; int ii;
    if (isMem) {
        v  = (tx < 8) ? g_mkv[(size_t)bp * 8 + tx] : -INFINITY;
        ii = (tx < 8) ? g_mki[(size_t)bp * 8 + tx] : 0;
    } else {
        v  = g_pkv[(size_t)bp * 32 + tx];
        ii = g_pki[(size_t)bp * 32 + tx];
    }

    float vals[8]; int ids[8];
#pragma unroll
    for (int k = 0; k < 8; ++k) {
        float m = v;
#pragma unroll
        for (int off = 16; off; off >>= 1)
            m = fmaxf(m, __shfl_xor_sync(FULL, m, off));
        unsigned ball = __ballot_sync(FULL, v == m);
        int sel = __ffs(ball) - 1;
        ids[k] = __shfl_sync(FULL, ii, sel);
        vals[k] = m;
        if (tx == sel) v = -INFINITY;
    }

    float mx = vals[0];
#pragma unroll
    for (int k = 1; k < 8; ++k) mx = fmaxf(mx, vals[k]);
    float wt[8], ssum = 0.f;
#pragma unroll
    for (int k = 0; k < 8; ++k) { wt[k] = expf(vals[k] - mx); ssum += wt[k]; }
    float inv = 1.f / ssum;
    float a0 = 0.f, a1 = 0.f;
#pragma unroll
    for (int k = 0; k < 8; ++k) {
        const float* vp = vb + (size_t)ids[k] * D_;
        float wk = wt[k] * inv;
        a0 += wk * vp[tx];
        a1 += wk * vp[tx + 32];
    }
    float* op = out + (isMem ? OFF4_ : OFF3_) + (size_t)bp * D_;
    op[tx] = a0;
    op[tx + 32] = a1;
}

// ---------------------------------------------------------------------------
__global__ void pre1_kernel() {
    int i = blockIdx.x * blockDim.x + threadIdx.x;
    if (i < B_ * HW_) g_winner[i] = -1;
    if (i < B_ * BITW) g_bitmap[i] = 0u;
}
__global__ void pre2_kernel(const int* __restrict__ idx) {
    int i = blockIdx.x * blockDim.x + threadIdx.x;
    if (i < B_ * P_) {
        int b = i / P_;
        int col = idx[i];
        atomicMax(&g_winner[b * HW_ + col], i - b * P_);
        atomicOr(&g_bitmap[b * BITW + (col >> 5)], 1u << (col & 31));
    }
}

// pos planes: winner pillars write pos_mem -> out0 upper, pos_point -> out1 upper
__global__ void __launch_bounds__(256)
pos_scatter_kernel(const int* __restrict__ idx, float* __restrict__ out)
{
    const int warp0 = blockIdx.x * 8 + (threadIdx.x >> 5);
    const int tx = threadIdx.x & 31;
    for (int bp = warp0; bp < B_ * P_; bp += gridDim.x * 8) {
        int b = (bp >= P_) ? 1 : 0;
        int p = bp - b * P_;
        int col = idx[bp];
        if (g_winner[b * HW_ + col] != p) continue;
        float mv0 = out[OFF4_ + (size_t)bp * D_ + tx];
        float mv1 = out[OFF4_ + (size_t)bp * D_ + tx + 32];
        float qv0 = out[OFF3_ + (size_t)bp * D_ + tx];
        float qv1 = out[OFF3_ + (size_t)bp * D_ + tx + 32];
        size_t g0 = (size_t)b * 128 * HW_ + (size_t)(64 + tx) * HW_ + col;
        out[g0] = mv0;
        out[g0 + (size_t)32 * HW_] = mv1;
        out[OFF1_ + g0] = qv0;
        out[OFF1_ + g0 + (size_t)32 * HW_] = qv1;
    }
}

// ---------------------------------------------------------------------------
extern "C" void kernel_launch(void* const* d_in, const int* in_sizes, int n_in,
                              void* d_out, int out_size) {
    (void)in_sizes; (void)n_in; (void)out_size;
    const float* pillars = (const float*)d_in[0];
    const float* scale   = (const float*)d_in[1];
    const float* points  = (const float*)d_in[2];
    const float* W       = (const float*)d_in[3];
    const int*   idx     = (const int*)d_in[4];
    float* out = (float*)d_out;

    cudaFuncSetAttribute(fused_kernel,
                         cudaFuncAttributeMaxDynamicSharedMemorySize, SMEM_BYTES);

    pre1_kernel<<<(B_ * HW_ + 255) / 256, 256>>>();
    pre2_kernel<<<(B_ * P_ + 255) / 256, 256>>>(idx);
    fused_kernel<<<NB_TOT, NTHR, SMEM_BYTES>>>(pillars, scale, points, W, out);
    merge_kernel<<<(2 * B_ * P_ + 7) / 8, 256>>>(points, W, out);
    pos_scatter_kernel<<<125, 256>>>(idx, out);
}

// round 12
// speedup vs baseline: 1.4978x; 1.3196x over previous
#include <cuda_runtime.h>
#include <math.h>

// ---------------------------------------------------------------------------
// Problem constants
// ---------------------------------------------------------------------------
#define B_   2
#define P_   4000
#define NP_  4096
#define D_   64
#define M_   512
#define HW_  214272
#define BITW (HW_ / 32)           // 6696

#define S0_   ((size_t)B_ * 128 * HW_)
#define S2_   ((size_t)B_ * 64 * HW_)
#define OFF1_ (S0_)
#define OFF2_ (2 * S0_)
#define OFF3_ (2 * S0_ + S2_)
#define OFF4_ (OFF3_ + (size_t)B_ * P_ * D_)

// Tiling (identical to the 440us R2 kernel)
#define TILE_P 64
#define TILE_T 128
#define PITCH  68        // 272 B rows; conflict-free LDS.128, 16B aligned
#define NTHR   256
#define PTILES 63                       // ceil(4000/64)
#define NB_PT  (PTILES * B_)            // 126
#define NB_MEM (PTILES * B_)            // 126
#define NB_ATT (NB_PT + NB_MEM)         // 252
#define NB_F   296                      // fill blocks
#define NB_TOT (2 * NB_ATT + (NB_F - NB_ATT))   // 548

#define PLANE4 (HW_ / 4)                // 53568
#define N4_    ((size_t)640 * PLANE4)   // 34,283,520 float4 to fill
#define FCH    115824                   // ceil(N4_/NB_F)

// dynamic shared layout (bytes) -- attention role; fill role uses first 53568B
#define SM_PL   0                                   // 64*68*4      = 17408
#define SM_PT   17408                               // 2*128*68*4   = 69632
#define SM_TKV  87040                               // 64*8*4       =  2048
#define SM_TKI  89088                               // 64*8*4       =  2048
#define SMEM_BYTES 91136

__device__ int      g_winner[B_ * HW_];
__device__ unsigned g_bitmap[B_ * BITW];

// ---------------------------------------------------------------------------
__device__ __forceinline__ void cp16(void* dst, const void* src) {
    unsigned a = (unsigned)__cvta_generic_to_shared(dst);
    asm volatile("cp.async.cg.shared.global [%0], [%1], 16;" :: "r"(a), "l"(src));
}
__device__ __forceinline__ void cp_commit() {
    asm volatile("cp.async.commit_group;" ::: "memory");
}
__device__ __forceinline__ void cp_wait_all() {
    asm volatile("cp.async.wait_group 0;" ::: "memory");
}
// packed f32x2 FMA
__device__ __forceinline__ void fma2(unsigned long long& acc,
                                     unsigned long long a, unsigned long long b) {
    asm volatile("fma.rn.f32x2 %0, %1, %2, %0;" : "+l"(acc) : "l"(a), "l"(b));
}

// ---------------------------------------------------------------------------
// Attention block — IDENTICAL to the R2 kernel that measured 350us fused.
// 64 pillars x npts, top-8 + softmax + weighted gather. 8 warps; warp wy owns
// pillars [wy*8, wy*8+8); lane tx owns point rows {tx+32j}.
// ---------------------------------------------------------------------------
__device__ void attn_block(const float* __restrict__ pillars,
                           const float* __restrict__ vecs,
                           int vstride, int npts,
                           float* __restrict__ out_pos,
                           int bid, char* smem)
{
    float* s_pl  = (float*)(smem + SM_PL);
    float* s_pt  = (float*)(smem + SM_PT);
    float* s_tkv = (float*)(smem + SM_TKV);
    int*   s_tki = (int*)(smem + SM_TKI);

    const int t  = threadIdx.x;
    const int tx = t & 31;
    const int wy = t >> 5;
    const int b  = bid / PTILES;
    const int p0 = (bid % PTILES) * TILE_P;
    const int pvalid = min(TILE_P, P_ - p0);
    const float* __restrict__ vb = vecs + (size_t)b * vstride;
    const float* __restrict__ pb = pillars + ((size_t)b * P_ + p0) * D_;
    const unsigned FULL = 0xffffffffu;

    s_tkv[t]       = -INFINITY;
    s_tkv[t + 256] = -INFINITY;

#pragma unroll
    for (int q = 0; q < 8; ++q) {
        int lin = t + q * NTHR;
        int r = lin >> 4, c = (lin & 15) << 2;
        cp16(s_pt + r * PITCH + c, vb + r * D_ + c);
    }
    cp_commit();

#pragma unroll
    for (int q = 0; q < 4; ++q) {
        int lin = t + q * NTHR;
        int r = lin >> 4, c = (lin & 15) << 2;
        float4 v = make_float4(0.f, 0.f, 0.f, 0.f);
        if (r < pvalid) v = *(const float4*)(pb + r * D_ + c);
        *(float4*)(s_pl + r * PITCH + c) = v;
    }
    __syncthreads();

    float vmin[8];
#pragma unroll
    for (int i = 0; i < 8; ++i) vmin[i] = -INFINITY;

    const int NT = npts / TILE_T;
    for (int tile = 0; tile < NT; ++tile) {
        float* buf = s_pt + (tile & 1) * (TILE_T * PITCH);
        cp_wait_all();
        __syncthreads();
        if (tile + 1 < NT) {
            float* nb = s_pt + ((tile + 1) & 1) * (TILE_T * PITCH);
            const float* src = vb + (size_t)(tile + 1) * TILE_T * D_;
#pragma unroll
            for (int q = 0; q < 8; ++q) {
                int lin = t + q * NTHR;
                int r = lin >> 4, c = (lin & 15) << 2;
                cp16(nb + r * PITCH + c, src + r * D_ + c);
            }
            cp_commit();
        }

        unsigned long long acc[8][4];
#pragma unroll
        for (int i = 0; i < 8; ++i)
#pragma unroll
            for (int j = 0; j < 4; ++j) acc[i][j] = 0ull;

#pragma unroll
        for (int dc = 0; dc < D_; dc += 4) {
            unsigned long long a0[8], a1[8], x0[4], x1[4];
#pragma unroll
            for (int i = 0; i < 8; ++i) {
                ulonglong2 v = *(const ulonglong2*)(s_pl + ((wy << 3) + i) * PITCH + dc);
                a0[i] = v.x; a1[i] = v.y;
            }
#pragma unroll
            for (int j = 0; j < 4; ++j) {
                ulonglong2 v = *(const ulonglong2*)(buf + (tx + 32 * j) * PITCH + dc);
                x0[j] = v.x; x1[j] = v.y;
            }
#pragma unroll
            for (int i = 0; i < 8; ++i)
#pragma unroll
                for (int j = 0; j < 4; ++j) {
                    fma2(acc[i][j], a0[i], x0[j]);
                    fma2(acc[i][j], a1[i], x1[j]);
                }
        }

        const int base = tile * TILE_T;
#pragma unroll
        for (int i = 0; i < 8; ++i) {
            const int pr = (wy << 3) + i;
            float thr = vmin[i];
            float s[4];
#pragma unroll
            for (int j = 0; j < 4; ++j) {
                unsigned long long v = acc[i][j];
                s[j] = __uint_as_float((unsigned)v) +
                       __uint_as_float((unsigned)(v >> 32));
            }
            unsigned any = __ballot_sync(FULL,
                (s[0] > thr) | (s[1] > thr) | (s[2] > thr) | (s[3] > thr));
            if (any) {
                float* tv = s_tkv + pr * 8;
                int*   ti = s_tki + pr * 8;
#pragma unroll
                for (int j = 0; j < 4; ++j) {
                    unsigned m = __ballot_sync(FULL, s[j] > thr);
                    while (m) {
                        int ln = __ffs(m) - 1; m &= m - 1;
                        float v = __shfl_sync(FULL, s[j], ln);
                        if (v > thr) {
                            int slot = 0; float mn = tv[0];
#pragma unroll
                            for (int k = 1; k < 8; ++k) {
                                float x = tv[k];
                                if (x < mn) { mn = x; slot = k; }
                            }
                            tv[slot] = v;
                            ti[slot] = base + ln + 32 * j;
                            thr = tv[0];
#pragma unroll
                            for (int k = 1; k < 8; ++k) thr = fminf(thr, tv[k]);
                        }
                    }
                }
                vmin[i] = thr;
            }
        }
    }

    __syncwarp();
#pragma unroll 1
    for (int i = 0; i < 8; ++i) {
        const int pr = (wy << 3) + i;
        if (pr >= pvalid) break;
        float vals[8]; int id[8];
#pragma unroll
        for (int k = 0; k < 8; ++k) { vals[k] = s_tkv[pr * 8 + k]; id[k] = s_tki[pr * 8 + k]; }
        float mx = vals[0];
#pragma unroll
        for (int k = 1; k < 8; ++k) mx = fmaxf(mx, vals[k]);
        float w[8], ssum = 0.f;
#pragma unroll
        for (int k = 0; k < 8; ++k) { w[k] = expf(vals[k] - mx); ssum += w[k]; }
        float inv = 1.f / ssum;
        float a0 = 0.f, a1 = 0.f;
#pragma unroll
        for (int k = 0; k < 8; ++k) {
            const float* vp = vb + (size_t)id[k] * D_;
            float wk = w[k] * inv;
            a0 += wk * vp[tx];
            a1 += wk * vp[tx + 32];
        }
        float* op = out_pos + ((size_t)b * P_ + p0 + pr) * D_;
        op[tx] = a0;
        op[tx + 32] = a1;
    }
}

// ---------------------------------------------------------------------------
// Fill role (verified in R10/R11): contiguous float4 range; static planes get
// winner values (pillars / scale) via smem bitmap, everything else zero.
// Planes: [0,256) out0, [256,512) out1 (ch<64 static; ch>=64 zeroed here and
// overwritten by pos_scatter), [512,640) out2 = scale.
// ---------------------------------------------------------------------------
__device__ void fill_range(int fid, const float* __restrict__ pillars,
                           const float* __restrict__ scale,
                           float* __restrict__ out, char* smem)
{
    unsigned* s_bm = (unsigned*)smem;
    const int t = threadIdx.x;
    for (int i = t; i < B_ * BITW; i += NTHR) s_bm[i] = g_bitmap[i];
    __syncthreads();

    size_t beg = (size_t)fid * FCH;
    size_t end = beg + FCH; if (end > N4_) end = N4_;
    float4* o4 = (float4*)out;

    for (size_t f = beg + t; f < end; f += NTHR) {
        int plane = (int)(f / PLANE4);          // 0..639
        int col4  = ((int)(f - (size_t)plane * PLANE4)) << 2;
        float4 v = make_float4(0.f, 0.f, 0.f, 0.f);
        int b, ch;
        const float* src;
        bool stat;
        if (plane < 512) {
            int pl = plane & 255;
            b = pl >> 7; ch = pl & 127;
            stat = ch < 64; src = pillars;
        } else {
            int pl = plane - 512;
            b = pl >> 6; ch = pl & 63;
            stat = true; src = scale;
        }
        if (stat) {
            unsigned bits = (s_bm[b * BITW + (col4 >> 5)] >> (col4 & 31)) & 0xFu;
            if (bits) {
                int colb = b * HW_ + col4;
                if (bits & 1u) { int w = g_winner[colb];     v.x = src[((size_t)(b * P_ + w)) * D_ + ch]; }
                if (bits & 2u) { int w = g_winner[colb + 1]; v.y = src[((size_t)(b * P_ + w)) * D_ + ch]; }
                if (bits & 4u) { int w = g_winner[colb + 2]; v.z = src[((size_t)(b * P_ + w)) * D_ + ch]; }
                if (bits & 8u) { int w = g_winner[colb + 3]; v.w = src[((size_t)(b * P_ + w)) * D_ + ch]; }
            }
        }
        __stcs(o4 + f, v);
    }
}

// ---------------------------------------------------------------------------
// Fused kernel — R2's interleave: bid<504: even -> attn bid/2, odd -> fill
// bid/2; bid in [504,548): fill 252+(bid-504).
// ---------------------------------------------------------------------------
__global__ void __launch_bounds__(NTHR, 2)
fused_kernel(const float* __restrict__ pillars,
             const float* __restrict__ scale,
             const float* __restrict__ points,
             const float* __restrict__ W,
             float* __restrict__ out)
{
    extern __shared__ char smem[];
    const int bid = blockIdx.x;
    int attn_id = -1, fid;
    if (bid < 2 * NB_ATT) {
        if ((bid & 1) == 0) attn_id = bid >> 1;
        else                fid = bid >> 1;
    } else {
        fid = NB_ATT + (bid - 2 * NB_ATT);
    }

    if (attn_id >= 0) {
        const int isMem = attn_id >= NB_PT;
        const int abid = isMem ? attn_id - NB_PT : attn_id;
        attn_block(pillars,
                   isMem ? W : points,
                   isMem ? 0 : NP_ * D_,
                   isMem ? M_ : NP_,
                   out + (isMem ? OFF4_ : OFF3_),
                   abid, smem);
    } else {
        fill_range(fid, pillars, scale, out, smem);
    }
}

// ---------------------------------------------------------------------------
__global__ void pre1_kernel() {
    int i = blockIdx.x * blockDim.x + threadIdx.x;
    if (i < B_ * HW_) g_winner[i] = -1;
    if (i < B_ * BITW) g_bitmap[i] = 0u;
}
__global__ void pre2_kernel(const int* __restrict__ idx) {
    int i = blockIdx.x * blockDim.x + threadIdx.x;
    if (i < B_ * P_) {
        int b = i / P_;
        int col = idx[i];
        atomicMax(&g_winner[b * HW_ + col], i - b * P_);
        atomicOr(&g_bitmap[b * BITW + (col >> 5)], 1u << (col & 31));
    }
}

// pos planes: winner pillars write pos_mem -> out0 upper, pos_point -> out1
// upper (verified in R10/R11).
__global__ void __launch_bounds__(256)
pos_scatter_kernel(const int* __restrict__ idx, float* __restrict__ out)
{
    const int warp0 = blockIdx.x * 8 + (threadIdx.x >> 5);
    const int tx = threadIdx.x & 31;
    for (int bp = warp0; bp < B_ * P_; bp += gridDim.x * 8) {
        int b = (bp >= P_) ? 1 : 0;
        int p = bp - b * P_;
        int col = idx[bp];
        if (g_winner[b * HW_ + col] != p) continue;
        float mv0 = out[OFF4_ + (size_t)bp * D_ + tx];
        float mv1 = out[OFF4_ + (size_t)bp * D_ + tx + 32];
        float qv0 = out[OFF3_ + (size_t)bp * D_ + tx];
        float qv1 = out[OFF3_ + (size_t)bp * D_ + tx + 32];
        size_t g0 = (size_t)b * 128 * HW_ + (size_t)(64 + tx) * HW_ + col;
        out[g0] = mv0;
        out[g0 + (size_t)32 * HW_] = mv1;
        out[OFF1_ + g0] = qv0;
        out[OFF1_ + g0 + (size_t)32 * HW_] = qv1;
    }
}

// ---------------------------------------------------------------------------
extern "C" void kernel_launch(void* const* d_in, const int* in_sizes, int n_in,
                              void* d_out, int out_size) {
    (void)in_sizes; (void)n_in; (void)out_size;
    const float* pillars = (const float*)d_in[0];
    const float* scale   = (const float*)d_in[1];
    const float* points  = (const float*)d_in[2];
    const float* W       = (const float*)d_in[3];
    const int*   idx     = (const int*)d_in[4];
    float* out = (float*)d_out;

    cudaFuncSetAttribute(fused_kernel,
                         cudaFuncAttributeMaxDynamicSharedMemorySize, SMEM_BYTES);

    pre1_kernel<<<(B_ * HW_ + 255) / 256, 256>>>();
    pre2_kernel<<<(B_ * P_ + 255) / 256, 256>>>(idx);
    fused_kernel<<<NB_TOT, NTHR, SMEM_BYTES>>>(pillars, scale, points, W, out);
    pos_scatter_kernel<<<125, 256>>>(idx, out);
}

// round 13
// speedup vs baseline: 1.7745x; 1.1847x over previous
#include <cuda_runtime.h>
#include <math.h>

// ---------------------------------------------------------------------------
// Problem constants
// ---------------------------------------------------------------------------
#define B_   2
#define P_   4000
#define NP_  4096
#define D_   64
#define M_   512
#define HW_  214272
#define BITW (HW_ / 32)           // 6696

#define S0_   ((size_t)B_ * 128 * HW_)
#define S2_   ((size_t)B_ * 64 * HW_)
#define OFF1_ (S0_)
#define OFF2_ (2 * S0_)
#define OFF3_ (2 * S0_ + S2_)
#define OFF4_ (OFF3_ + (size_t)B_ * P_ * D_)

// Tiling (identical to the R2 kernel whose fused measured 350us)
#define TILE_P 64
#define TILE_T 128
#define PITCH  68        // 272 B rows; conflict-free LDS.128, 16B aligned
#define NTHR   256
#define PTILES 63                       // ceil(4000/64)
#define NB_PT  (PTILES * B_)            // 126
#define NB_MEM (PTILES * B_)            // 126
#define NB_ATT (NB_PT + NB_MEM)         // 252
#define NB_F   296                      // fill blocks
#define NB_TOT (2 * NB_ATT + (NB_F - NB_ATT))   // 548

#define PLANE4 (HW_ / 4)                // 53568 float4 per plane
#define QUART4 (PLANE4 / 4)             // 13392 float4 per chunk
#define NCHUNK (640 * 4)                // 2560 chunks total

// dynamic shared layout (bytes) -- attention role; fill role uses first 53568B
#define SM_PL   0                                   // 64*68*4      = 17408
#define SM_PT   17408                               // 2*128*68*4   = 69632
#define SM_TKV  87040                               // 64*8*4       =  2048
#define SM_TKI  89088                               // 64*8*4       =  2048
#define SMEM_BYTES 91136

__device__ int      g_winner[B_ * HW_];
__device__ unsigned g_bitmap[B_ * BITW];

// ---------------------------------------------------------------------------
__device__ __forceinline__ void cp16(void* dst, const void* src) {
    unsigned a = (unsigned)__cvta_generic_to_shared(dst);
    asm volatile("cp.async.cg.shared.global [%0], [%1], 16;" :: "r"(a), "l"(src));
}
__device__ __forceinline__ void cp_commit() {
    asm volatile("cp.async.commit_group;" ::: "memory");
}
__device__ __forceinline__ void cp_wait_all() {
    asm volatile("cp.async.wait_group 0;" ::: "memory");
}
__device__ __forceinline__ void fma2(unsigned long long& acc,
                                     unsigned long long a, unsigned long long b) {
    asm volatile("fma.rn.f32x2 %0, %1, %2, %0;" : "+l"(acc) : "l"(a), "l"(b));
}

// ---------------------------------------------------------------------------
// Attention block — byte-identical logic to the R2 kernel (fused 350us).
// ---------------------------------------------------------------------------
__device__ void attn_block(const float* __restrict__ pillars,
                           const float* __restrict__ vecs,
                           int vstride, int npts,
                           float* __restrict__ out_pos,
                           int bid, char* smem)
{
    float* s_pl  = (float*)(smem + SM_PL);
    float* s_pt  = (float*)(smem + SM_PT);
    float* s_tkv = (float*)(smem + SM_TKV);
    int*   s_tki = (int*)(smem + SM_TKI);

    const int t  = threadIdx.x;
    const int tx = t & 31;
    const int wy = t >> 5;
    const int b  = bid / PTILES;
    const int p0 = (bid % PTILES) * TILE_P;
    const int pvalid = min(TILE_P, P_ - p0);
    const float* __restrict__ vb = vecs + (size_t)b * vstride;
    const float* __restrict__ pb = pillars + ((size_t)b * P_ + p0) * D_;
    const unsigned FULL = 0xffffffffu;

    s_tkv[t]       = -INFINITY;
    s_tkv[t + 256] = -INFINITY;

#pragma unroll
    for (int q = 0; q < 8; ++q) {
        int lin = t + q * NTHR;
        int r = lin >> 4, c = (lin & 15) << 2;
        cp16(s_pt + r * PITCH + c, vb + r * D_ + c);
    }
    cp_commit();

#pragma unroll
    for (int q = 0; q < 4; ++q) {
        int lin = t + q * NTHR;
        int r = lin >> 4, c = (lin & 15) << 2;
        float4 v = make_float4(0.f, 0.f, 0.f, 0.f);
        if (r < pvalid) v = *(const float4*)(pb + r * D_ + c);
        *(float4*)(s_pl + r * PITCH + c) = v;
    }
    __syncthreads();

    float vmin[8];
#pragma unroll
    for (int i = 0; i < 8; ++i) vmin[i] = -INFINITY;

    const int NT = npts / TILE_T;
    for (int tile = 0; tile < NT; ++tile) {
        float* buf = s_pt + (tile & 1) * (TILE_T * PITCH);
        cp_wait_all();
        __syncthreads();
        if (tile + 1 < NT) {
            float* nb = s_pt + ((tile + 1) & 1) * (TILE_T * PITCH);
            const float* src = vb + (size_t)(tile + 1) * TILE_T * D_;
#pragma unroll
            for (int q = 0; q < 8; ++q) {
                int lin = t + q * NTHR;
                int r = lin >> 4, c = (lin & 15) << 2;
                cp16(nb + r * PITCH + c, src + r * D_ + c);
            }
            cp_commit();
        }

        unsigned long long acc[8][4];
#pragma unroll
        for (int i = 0; i < 8; ++i)
#pragma unroll
            for (int j = 0; j < 4; ++j) acc[i][j] = 0ull;

#pragma unroll
        for (int dc = 0; dc < D_; dc += 4) {
            unsigned long long a0[8], a1[8], x0[4], x1[4];
#pragma unroll
            for (int i = 0; i < 8; ++i) {
                ulonglong2 v = *(const ulonglong2*)(s_pl + ((wy << 3) + i) * PITCH + dc);
                a0[i] = v.x; a1[i] = v.y;
            }
#pragma unroll
            for (int j = 0; j < 4; ++j) {
                ulonglong2 v = *(const ulonglong2*)(buf + (tx + 32 * j) * PITCH + dc);
                x0[j] = v.x; x1[j] = v.y;
            }
#pragma unroll
            for (int i = 0; i < 8; ++i)
#pragma unroll
                for (int j = 0; j < 4; ++j) {
                    fma2(acc[i][j], a0[i], x0[j]);
                    fma2(acc[i][j], a1[i], x1[j]);
                }
        }

        const int base = tile * TILE_T;
#pragma unroll
        for (int i = 0; i < 8; ++i) {
            const int pr = (wy << 3) + i;
            float thr = vmin[i];
            float s[4];
#pragma unroll
            for (int j = 0; j < 4; ++j) {
                unsigned long long v = acc[i][j];
                s[j] = __uint_as_float((unsigned)v) +
                       __uint_as_float((unsigned)(v >> 32));
            }
            unsigned any = __ballot_sync(FULL,
                (s[0] > thr) | (s[1] > thr) | (s[2] > thr) | (s[3] > thr));
            if (any) {
                float* tv = s_tkv + pr * 8;
                int*   ti = s_tki + pr * 8;
#pragma unroll
                for (int j = 0; j < 4; ++j) {
                    unsigned m = __ballot_sync(FULL, s[j] > thr);
                    while (m) {
                        int ln = __ffs(m) - 1; m &= m - 1;
                        float v = __shfl_sync(FULL, s[j], ln);
                        if (v > thr) {
                            int slot = 0; float mn = tv[0];
#pragma unroll
                            for (int k = 1; k < 8; ++k) {
                                float x = tv[k];
                                if (x < mn) { mn = x; slot = k; }
                            }
                            tv[slot] = v;
                            ti[slot] = base + ln + 32 * j;
                            thr = tv[0];
#pragma unroll
                            for (int k = 1; k < 8; ++k) thr = fminf(thr, tv[k]);
                        }
                    }
                }
                vmin[i] = thr;
            }
        }
    }

    __syncwarp();
#pragma unroll 1
    for (int i = 0; i < 8; ++i) {
        const int pr = (wy << 3) + i;
        if (pr >= pvalid) break;
        float vals[8]; int id[8];
#pragma unroll
        for (int k = 0; k < 8; ++k) { vals[k] = s_tkv[pr * 8 + k]; id[k] = s_tki[pr * 8 + k]; }
        float mx = vals[0];
#pragma unroll
        for (int k = 1; k < 8; ++k) mx = fmaxf(mx, vals[k]);
        float w[8], ssum = 0.f;
#pragma unroll
        for (int k = 0; k < 8; ++k) { w[k] = expf(vals[k] - mx); ssum += w[k]; }
        float inv = 1.f / ssum;
        float a0 = 0.f, a1 = 0.f;
#pragma unroll
        for (int k = 0; k < 8; ++k) {
            const float* vp = vb + (size_t)id[k] * D_;
            float wk = w[k] * inv;
            a0 += wk * vp[tx];
            a1 += wk * vp[tx + 32];
        }
        float* op = out_pos + ((size_t)b * P_ + p0 + pr) * D_;
        op[tx] = a0;
        op[tx + 32] = a1;
    }
}

// ---------------------------------------------------------------------------
// Fill role, chunk-structured. Chunk = (plane, quarter); plane decode hoisted
// out of the inner loop. Pure-zero planes: 2-inst streaming loop. Static
// planes: one smem bitmap-word load + nibble test per float4.
// ---------------------------------------------------------------------------
__device__ void fill_role(int fid, const float* __restrict__ pillars,
                          const float* __restrict__ scale,
                          float* __restrict__ out, char* smem)
{
    unsigned* s_bm = (unsigned*)smem;
    const int t = threadIdx.x;
    for (int i = t; i < B_ * BITW; i += NTHR) s_bm[i] = g_bitmap[i];
    __syncthreads();

    const float4 z = make_float4(0.f, 0.f, 0.f, 0.f);

    for (int c = fid; c < NCHUNK; c += NB_F) {
        const int plane = c >> 2;
        const int q0 = (c & 3) * QUART4;
        float4* __restrict__ dst = (float4*)out + (size_t)plane * PLANE4;

        int b, ch;
        const float* src;
        bool stat;
        if (plane < 512) {
            int pl = plane & 255;
            b = pl >> 7; ch = pl & 127;
            stat = ch < 64; src = pillars;
        } else {
            int pl = plane - 512;
            b = pl >> 6; ch = pl & 63;
            stat = true; src = scale;
        }

        if (!stat) {
            // pure zero plane quarter: tight streaming loop
#pragma unroll 4
            for (int f = q0 + t; f < q0 + QUART4; f += NTHR)
                __stcs(dst + f, z);
        } else {
            const unsigned* bm = s_bm + b * BITW;
            const int* win = g_winner + b * HW_;
            const float* sp = src + (size_t)b * P_ * D_ + ch;
            for (int f = q0 + t; f < q0 + QUART4; f += NTHR) {
                float4 v = z;
                unsigned bits = (bm[f >> 3] >> ((f & 7) * 4)) & 0xFu;
                if (bits) {
                    int col = f << 2;
                    if (bits & 1u) v.x = sp[(size_t)win[col]     * D_];
                    if (bits & 2u) v.y = sp[(size_t)win[col + 1] * D_];
                    if (bits & 4u) v.z = sp[(size_t)win[col + 2] * D_];
                    if (bits & 8u) v.w = sp[(size_t)win[col + 3] * D_];
                }
                __stcs(dst + f, v);
            }
        }
    }
}

// ---------------------------------------------------------------------------
// Fused kernel — R2's interleave: bid<504: even -> attn bid/2, odd -> fill
// bid/2; bid in [504,548): fill 252+(bid-504).
// ---------------------------------------------------------------------------
__global__ void __launch_bounds__(NTHR, 2)
fused_kernel(const float* __restrict__ pillars,
             const float* __restrict__ scale,
             const float* __restrict__ points,
             const float* __restrict__ W,
             float* __restrict__ out)
{
    extern __shared__ char smem[];
    const int bid = blockIdx.x;
    int attn_id = -1, fid;
    if (bid < 2 * NB_ATT) {
        if ((bid & 1) == 0) attn_id = bid >> 1;
        else                fid = bid >> 1;
    } else {
        fid = NB_ATT + (bid - 2 * NB_ATT);
    }

    if (attn_id >= 0) {
        const int isMem = attn_id >= NB_PT;
        const int abid = isMem ? attn_id - NB_PT : attn_id;
        attn_block(pillars,
                   isMem ? W : points,
                   isMem ? 0 : NP_ * D_,
                   isMem ? M_ : NP_,
                   out + (isMem ? OFF4_ : OFF3_),
                   abid, smem);
    } else {
        fill_role(fid, pillars, scale, out, smem);
    }
}

// ---------------------------------------------------------------------------
__global__ void pre1_kernel() {
    int i = blockIdx.x * blockDim.x + threadIdx.x;
    if (i < B_ * HW_) g_winner[i] = -1;
    if (i < B_ * BITW) g_bitmap[i] = 0u;
}
__global__ void pre2_kernel(const int* __restrict__ idx) {
    int i = blockIdx.x * blockDim.x + threadIdx.x;
    if (i < B_ * P_) {
        int b = i / P_;
        int col = idx[i];
        atomicMax(&g_winner[b * HW_ + col], i - b * P_);
        atomicOr(&g_bitmap[b * BITW + (col >> 5)], 1u << (col & 31));
    }
}

// pos planes: winner pillars write pos_mem -> out0 upper, pos_point -> out1
// upper. One warp per pillar, 1000 blocks (occupancy fix: was 125).
__global__ void __launch_bounds__(256)
pos_scatter_kernel(const int* __restrict__ idx, float* __restrict__ out)
{
    const int bp = blockIdx.x * 8 + (threadIdx.x >> 5);
    const int tx = threadIdx.x & 31;
    if (bp >= B_ * P_) return;
    int b = (bp >= P_) ? 1 : 0;
    int p = bp - b * P_;
    int col = idx[bp];
    if (g_winner[b * HW_ + col] != p) return;
    float mv0 = out[OFF4_ + (size_t)bp * D_ + tx];
    float mv1 = out[OFF4_ + (size_t)bp * D_ + tx + 32];
    float qv0 = out[OFF3_ + (size_t)bp * D_ + tx];
    float qv1 = out[OFF3_ + (size_t)bp * D_ + tx + 32];
    size_t g0 = (size_t)b * 128 * HW_ + (size_t)(64 + tx) * HW_ + col;
    out[g0] = mv0;
    out[g0 + (size_t)32 * HW_] = mv1;
    out[OFF1_ + g0] = qv0;
    out[OFF1_ + g0 + (size_t)32 * HW_] = qv1;
}

// ---------------------------------------------------------------------------
extern "C" void kernel_launch(void* const* d_in, const int* in_sizes, int n_in,
                              void* d_out, int out_size) {
    (void)in_sizes; (void)n_in; (void)out_size;
    const float* pillars = (const float*)d_in[0];
    const float* scale   = (const float*)d_in[1];
    const float* points  = (const float*)d_in[2];
    const float* W       = (const float*)d_in[3];
    const int*   idx     = (const int*)d_in[4];
    float* out = (float*)d_out;

    cudaFuncSetAttribute(fused_kernel,
                         cudaFuncAttributeMaxDynamicSharedMemorySize, SMEM_BYTES);

    pre1_kernel<<<(B_ * HW_ + 255) / 256, 256>>>();
    pre2_kernel<<<(B_ * P_ + 255) / 256, 256>>>(idx);
    fused_kernel<<<NB_TOT, NTHR, SMEM_BYTES>>>(pillars, scale, points, W, out);
    pos_scatter_kernel<<<1000, 256>>>(idx, out);
}

// round 14
// speedup vs baseline: 1.8816x; 1.0604x over previous
#include <cuda_runtime.h>
#include <math.h>

// ---------------------------------------------------------------------------
// Problem constants
// ---------------------------------------------------------------------------
#define B_   2
#define P_   4000
#define NP_  4096
#define D_   64
#define M_   512
#define HW_  214272
#define BITW (HW_ / 32)           // 6696

#define S0_   ((size_t)B_ * 128 * HW_)
#define S2_   ((size_t)B_ * 64 * HW_)
#define OFF1_ (S0_)
#define OFF2_ (2 * S0_)
#define OFF3_ (2 * S0_ + S2_)
#define OFF4_ (OFF3_ + (size_t)B_ * P_ * D_)

// Tiling (R2 lineage: fused attention measured ~350us)
#define TILE_P 64
#define TILE_T 128
#define PITCH  68        // 272 B rows; conflict-free LDS.128, 16B aligned
#define NTHR   256
#define PTILES 63                       // ceil(4000/64)
#define NB_PT  (PTILES * B_)            // 126
#define NB_MEM (PTILES * B_)            // 126
#define NB_ATT (NB_PT + NB_MEM)         // 252
#define NB_F   296                      // fill blocks
#define NB_TOT (2 * NB_ATT + (NB_F - NB_ATT))   // 548

#define PLANE4 (HW_ / 4)                // 53568 float4 per plane
#define QUART4 (PLANE4 / 4)             // 13392 float4 per chunk
#define NCHUNK (640 * 4)                // 2560 chunks total

// dynamic shared layout (bytes) -- attention role; fill role uses first 53568B
#define SM_PL   0                                   // 64*68*4      = 17408
#define SM_PT   17408                               // 2*128*68*4   = 69632
#define SM_TKV  87040                               // 64*8*4       =  2048
#define SM_TKI  89088                               // 64*8*4       =  2048
#define SMEM_BYTES 91136

__device__ int      g_winner[B_ * HW_];
__device__ unsigned g_bitmap[B_ * BITW];

// ---------------------------------------------------------------------------
__device__ __forceinline__ void cp16(void* dst, const void* src) {
    unsigned a = (unsigned)__cvta_generic_to_shared(dst);
    asm volatile("cp.async.cg.shared.global [%0], [%1], 16;" :: "r"(a), "l"(src));
}
__device__ __forceinline__ void cp_commit() {
    asm volatile("cp.async.commit_group;" ::: "memory");
}
__device__ __forceinline__ void cp_wait_all() {
    asm volatile("cp.async.wait_group 0;" ::: "memory");
}
__device__ __forceinline__ void fma2(unsigned long long& acc,
                                     unsigned long long a, unsigned long long b) {
    asm volatile("fma.rn.f32x2 %0, %1, %2, %0;" : "+l"(acc) : "l"(a), "l"(b));
}
__device__ __forceinline__ float pair_sum(unsigned long long v) {
    return __uint_as_float((unsigned)v) + __uint_as_float((unsigned)(v >> 32));
}

// ---------------------------------------------------------------------------
// Attention block (R2 core) + fused winner scatter in the epilogue.
// scat: base of the output tensor whose UPPER 64 planes this branch owns
//       (memory branch -> out0 at offset 0; point branch -> out1 at OFF1_).
// ---------------------------------------------------------------------------
__device__ void attn_block(const float* __restrict__ pillars,
                           const float* __restrict__ vecs,
                           int vstride, int npts,
                           float* __restrict__ out_pos,
                           float* __restrict__ scat,
                           const int* __restrict__ idx,
                           int bid, char* smem)
{
    float* s_pl  = (float*)(smem + SM_PL);
    float* s_pt  = (float*)(smem + SM_PT);
    float* s_tkv = (float*)(smem + SM_TKV);
    int*   s_tki = (int*)(smem + SM_TKI);

    const int t  = threadIdx.x;
    const int tx = t & 31;
    const int wy = t >> 5;
    const int b  = bid / PTILES;
    const int p0 = (bid % PTILES) * TILE_P;
    const int pvalid = min(TILE_P, P_ - p0);
    const float* __restrict__ vb = vecs + (size_t)b * vstride;
    const float* __restrict__ pb = pillars + ((size_t)b * P_ + p0) * D_;
    const unsigned FULL = 0xffffffffu;

    s_tkv[t]       = -INFINITY;
    s_tkv[t + 256] = -INFINITY;

#pragma unroll
    for (int q = 0; q < 8; ++q) {
        int lin = t + q * NTHR;
        int r = lin >> 4, c = (lin & 15) << 2;
        cp16(s_pt + r * PITCH + c, vb + r * D_ + c);
    }
    cp_commit();

#pragma unroll
    for (int q = 0; q < 4; ++q) {
        int lin = t + q * NTHR;
        int r = lin >> 4, c = (lin & 15) << 2;
        float4 v = make_float4(0.f, 0.f, 0.f, 0.f);
        if (r < pvalid) v = *(const float4*)(pb + r * D_ + c);
        *(float4*)(s_pl + r * PITCH + c) = v;
    }
    __syncthreads();

    float vmin[8];
#pragma unroll
    for (int i = 0; i < 8; ++i) vmin[i] = -INFINITY;

    const int NT = npts / TILE_T;
    for (int tile = 0; tile < NT; ++tile) {
        float* buf = s_pt + (tile & 1) * (TILE_T * PITCH);
        cp_wait_all();
        __syncthreads();
        if (tile + 1 < NT) {
            float* nb = s_pt + ((tile + 1) & 1) * (TILE_T * PITCH);
            const float* src = vb + (size_t)(tile + 1) * TILE_T * D_;
#pragma unroll
            for (int q = 0; q < 8; ++q) {
                int lin = t + q * NTHR;
                int r = lin >> 4, c = (lin & 15) << 2;
                cp16(nb + r * PITCH + c, src + r * D_ + c);
            }
            cp_commit();
        }

        unsigned long long acc[8][4];
#pragma unroll
        for (int i = 0; i < 8; ++i)
#pragma unroll
            for (int j = 0; j < 4; ++j) acc[i][j] = 0ull;

#pragma unroll
        for (int dc = 0; dc < D_; dc += 4) {
            unsigned long long a0[8], a1[8], x0[4], x1[4];
#pragma unroll
            for (int i = 0; i < 8; ++i) {
                ulonglong2 v = *(const ulonglong2*)(s_pl + ((wy << 3) + i) * PITCH + dc);
                a0[i] = v.x; a1[i] = v.y;
            }
#pragma unroll
            for (int j = 0; j < 4; ++j) {
                ulonglong2 v = *(const ulonglong2*)(buf + (tx + 32 * j) * PITCH + dc);
                x0[j] = v.x; x1[j] = v.y;
            }
#pragma unroll
            for (int i = 0; i < 8; ++i)
#pragma unroll
                for (int j = 0; j < 4; ++j) {
                    fma2(acc[i][j], a0[i], x0[j]);
                    fma2(acc[i][j], a1[i], x1[j]);
                }
        }

        // ---- top-8 maintenance: one batched ballot per tile ----
        const int base = tile * TILE_T;
        bool anyhit = false;
#pragma unroll
        for (int i = 0; i < 8; ++i) {
            float thr = vmin[i];
#pragma unroll
            for (int j = 0; j < 4; ++j)
                anyhit |= (pair_sum(acc[i][j]) > thr);
        }
        if (__ballot_sync(FULL, anyhit)) {
#pragma unroll
            for (int i = 0; i < 8; ++i) {
                const int pr = (wy << 3) + i;
                float thr = vmin[i];
                float s[4];
#pragma unroll
                for (int j = 0; j < 4; ++j) s[j] = pair_sum(acc[i][j]);
                unsigned any = __ballot_sync(FULL,
                    (s[0] > thr) | (s[1] > thr) | (s[2] > thr) | (s[3] > thr));
                if (any) {
                    float* tv = s_tkv + pr * 8;
                    int*   ti = s_tki + pr * 8;
#pragma unroll
                    for (int j = 0; j < 4; ++j) {
                        unsigned m = __ballot_sync(FULL, s[j] > thr);
                        while (m) {
                            int ln = __ffs(m) - 1; m &= m - 1;
                            float v = __shfl_sync(FULL, s[j], ln);
                            if (v > thr) {
                                int slot = 0; float mn = tv[0];
#pragma unroll
                                for (int k = 1; k < 8; ++k) {
                                    float x = tv[k];
                                    if (x < mn) { mn = x; slot = k; }
                                }
                                tv[slot] = v;
                                ti[slot] = base + ln + 32 * j;
                                thr = tv[0];
#pragma unroll
                                for (int k = 1; k < 8; ++k) thr = fminf(thr, tv[k]);
                            }
                        }
                    }
                    vmin[i] = thr;
                }
            }
        }
    }

    __syncwarp();
#pragma unroll 1
    for (int i = 0; i < 8; ++i) {
        const int pr = (wy << 3) + i;
        if (pr >= pvalid) break;
        float vals[8]; int id[8];
#pragma unroll
        for (int k = 0; k < 8; ++k) { vals[k] = s_tkv[pr * 8 + k]; id[k] = s_tki[pr * 8 + k]; }
        float mx = vals[0];
#pragma unroll
        for (int k = 1; k < 8; ++k) mx = fmaxf(mx, vals[k]);
        float w[8], ssum = 0.f;
#pragma unroll
        for (int k = 0; k < 8; ++k) { w[k] = expf(vals[k] - mx); ssum += w[k]; }
        float inv = 1.f / ssum;
        float a0 = 0.f, a1 = 0.f;
#pragma unroll
        for (int k = 0; k < 8; ++k) {
            const float* vp = vb + (size_t)id[k] * D_;
            float wk = w[k] * inv;
            a0 += wk * vp[tx];
            a1 += wk * vp[tx + 32];
        }
        const int p = p0 + pr;
        float* op = out_pos + ((size_t)b * P_ + p) * D_;
        op[tx] = a0;
        op[tx + 32] = a1;

        // fused winner scatter: this branch owns the upper planes of `scat`
        const int col = idx[b * P_ + p];
        if (g_winner[b * HW_ + col] == p) {
            size_t g0 = (size_t)b * 128 * HW_ + (size_t)(64 + tx) * HW_ + col;
            scat[g0] = a0;
            scat[g0 + (size_t)32 * HW_] = a1;
        }
    }
}

// ---------------------------------------------------------------------------
// Fill role, chunk-structured. Static planes (out0/out1 lower, out2): winner
// values from pillars/scale. Upper planes (out0/out1 ch>=64): zeros EXCEPT
// winner columns, which are skipped (the attention epilogues write them) --
// write-sets disjoint, no ordering needed.
// ---------------------------------------------------------------------------
__device__ void fill_role(int fid, const float* __restrict__ pillars,
                          const float* __restrict__ scale,
                          float* __restrict__ out, char* smem)
{
    unsigned* s_bm = (unsigned*)smem;
    const int t = threadIdx.x;
    for (int i = t; i < B_ * BITW; i += NTHR) s_bm[i] = g_bitmap[i];
    __syncthreads();

    const float4 z = make_float4(0.f, 0.f, 0.f, 0.f);

    for (int c = fid; c < NCHUNK; c += NB_F) {
        const int plane = c >> 2;
        const int q0 = (c & 3) * QUART4;
        float4* __restrict__ dst = (float4*)out + (size_t)plane * PLANE4;

        int b, ch;
        const float* src;
        bool stat;
        if (plane < 512) {
            int pl = plane & 255;
            b = pl >> 7; ch = pl & 127;
            stat = ch < 64; src = pillars;
        } else {
            int pl = plane - 512;
            b = pl >> 6; ch = pl & 63;
            stat = true; src = scale;
        }

        const unsigned* bm = s_bm + b * BITW;
        if (!stat) {
            // upper plane: zeros, skipping winner columns (epilogue writes them)
            for (int f = q0 + t; f < q0 + QUART4; f += NTHR) {
                unsigned bits = (bm[f >> 3] >> ((f & 7) * 4)) & 0xFu;
                if (!bits) {
                    __stcs(dst + f, z);
                } else {
                    float* d = (float*)(dst + f);
                    if (!(bits & 1u)) d[0] = 0.f;
                    if (!(bits & 2u)) d[1] = 0.f;
                    if (!(bits & 4u)) d[2] = 0.f;
                    if (!(bits & 8u)) d[3] = 0.f;
                }
            }
        } else {
            const int* win = g_winner + b * HW_;
            const float* sp = src + (size_t)b * P_ * D_ + ch;
            for (int f = q0 + t; f < q0 + QUART4; f += NTHR) {
                float4 v = z;
                unsigned bits = (bm[f >> 3] >> ((f & 7) * 4)) & 0xFu;
                if (bits) {
                    int col = f << 2;
                    if (bits & 1u) v.x = sp[(size_t)win[col]     * D_];
                    if (bits & 2u) v.y = sp[(size_t)win[col + 1] * D_];
                    if (bits & 4u) v.z = sp[(size_t)win[col + 2] * D_];
                    if (bits & 8u) v.w = sp[(size_t)win[col + 3] * D_];
                }
                __stcs(dst + f, v);
            }
        }
    }
}

// ---------------------------------------------------------------------------
// Fused kernel — interleave: bid<504: even -> attn bid/2, odd -> fill bid/2;
// bid in [504,548): fill 252+(bid-504).
// ---------------------------------------------------------------------------
__global__ void __launch_bounds__(NTHR, 2)
fused_kernel(const float* __restrict__ pillars,
             const float* __restrict__ scale,
             const float* __restrict__ points,
             const float* __restrict__ W,
             const int* __restrict__ idx,
             float* __restrict__ out)
{
    extern __shared__ char smem[];
    const int bid = blockIdx.x;
    int attn_id = -1, fid;
    if (bid < 2 * NB_ATT) {
        if ((bid & 1) == 0) attn_id = bid >> 1;
        else                fid = bid >> 1;
    } else {
        fid = NB_ATT + (bid - 2 * NB_ATT);
    }

    if (attn_id >= 0) {
        const int isMem = attn_id >= NB_PT;
        const int abid = isMem ? attn_id - NB_PT : attn_id;
        attn_block(pillars,
                   isMem ? W : points,
                   isMem ? 0 : NP_ * D_,
                   isMem ? M_ : NP_,
                   out + (isMem ? OFF4_ : OFF3_),
                   isMem ? out : out + OFF1_,     // mem -> out0 upper, point -> out1 upper
                   idx, abid, smem);
    } else {
        fill_role(fid, pillars, scale, out, smem);
    }
}

// ---------------------------------------------------------------------------
__global__ void pre1_kernel() {
    int i = blockIdx.x * blockDim.x + threadIdx.x;
    if (i < B_ * HW_) g_winner[i] = -1;
    if (i < B_ * BITW) g_bitmap[i] = 0u;
}
__global__ void pre2_kernel(const int* __restrict__ idx) {
    int i = blockIdx.x * blockDim.x + threadIdx.x;
    if (i < B_ * P_) {
        int b = i / P_;
        int col = idx[i];
        atomicMax(&g_winner[b * HW_ + col], i - b * P_);
        atomicOr(&g_bitmap[b * BITW + (col >> 5)], 1u << (col & 31));
    }
}

// ---------------------------------------------------------------------------
extern "C" void kernel_launch(void* const* d_in, const int* in_sizes, int n_in,
                              void* d_out, int out_size) {
    (void)in_sizes; (void)n_in; (void)out_size;
    const float* pillars = (const float*)d_in[0];
    const float* scale   = (const float*)d_in[1];
    const float* points  = (const float*)d_in[2];
    const float* W       = (const float*)d_in[3];
    const int*   idx     = (const int*)d_in[4];
    float* out = (float*)d_out;

    cudaFuncSetAttribute(fused_kernel,
                         cudaFuncAttributeMaxDynamicSharedMemorySize, SMEM_BYTES);

    pre1_kernel<<<(B_ * HW_ + 255) / 256, 256>>>();
    pre2_kernel<<<(B_ * P_ + 255) / 256, 256>>>(idx);
    fused_kernel<<<NB_TOT, NTHR, SMEM_BYTES>>>(pillars, scale, points, W, idx, out);
}